// round 11
// baseline (speedup 1.0000x reference)
#include <cuda_runtime.h>
#include <cuda_bf16.h>
#include <cstdint>

// Problem constants
#define VOCABN 50257
#define SMALLN 512
#define LARGEN 1024
#define NTOK   8192      // B*S = 4*2048

// int8 staging (device globals: allocation-free scratch)
__device__ int8_t g_Aq[NTOK * SMALLN];    // quantized gathered weight rows
__device__ int8_t g_Bq[SMALLN * SMALLN];  // quantized cw
__device__ float  g_sa[NTOK];             // per-token-row scale
__device__ float  g_sb[SMALLN];           // per-cw-row scale

// ---------------------------------------------------------------------------
// Kernel 1: warp-per-row prep.
//  rows [0, NTOK):        token rows -> out[t,0:512]=w[id]+r[id,0:512],
//                         rowmax-quantize w[id] -> g_Aq, g_sa
//  rows [NTOK, NTOK+512): cw rows -> quantize -> g_Bq, g_sb
// ---------------------------------------------------------------------------
#define PREP_WARPS (NTOK + SMALLN)        // 8704
#define PREP_BLOCKS (PREP_WARPS / 8)      // 1088 (256-thread blocks)

__global__ void prep_kernel(const int* __restrict__ ids,
                            const float4* __restrict__ w4,     // [VOCAB][128]
                            const float4* __restrict__ r4,     // [VOCAB][256]
                            const float4* __restrict__ cw4,    // [512][128]
                            float4* __restrict__ out4) {       // [NTOK][256]
    const int wg   = (blockIdx.x * blockDim.x + threadIdx.x) >> 5;
    const int lane = threadIdx.x & 31;

    float4 v[4];
    uint32_t* qdst;
    float* sdst;

    if (wg < NTOK) {
        const int id = ids[wg];
        const float4* wrow = w4 + (size_t)id * 128;
        const float4* rrow = r4 + (size_t)id * 256;
        #pragma unroll
        for (int j = 0; j < 4; j++) v[j] = wrow[j * 32 + lane];
        // first-half out = w + r
        #pragma unroll
        for (int j = 0; j < 4; j++) {
            float4 rv = rrow[j * 32 + lane];
            float4 o;
            o.x = v[j].x + rv.x; o.y = v[j].y + rv.y;
            o.z = v[j].z + rv.z; o.w = v[j].w + rv.w;
            out4[(size_t)wg * 256 + j * 32 + lane] = o;
        }
        qdst = reinterpret_cast<uint32_t*>(g_Aq) + (size_t)wg * 128;
        sdst = g_sa + wg;
    } else {
        const int n = wg - NTOK;          // 0..511
        const float4* crow = cw4 + (size_t)n * 128;
        #pragma unroll
        for (int j = 0; j < 4; j++) v[j] = crow[j * 32 + lane];
        qdst = reinterpret_cast<uint32_t*>(g_Bq) + (size_t)n * 128;
        sdst = g_sb + n;
    }

    // row max of |x|
    float m = 0.f;
    #pragma unroll
    for (int j = 0; j < 4; j++) {
        m = fmaxf(m, fmaxf(fmaxf(fabsf(v[j].x), fabsf(v[j].y)),
                           fmaxf(fabsf(v[j].z), fabsf(v[j].w))));
    }
    #pragma unroll
    for (int s = 16; s > 0; s >>= 1)
        m = fmaxf(m, __shfl_xor_sync(0xFFFFFFFFu, m, s));

    const float inv = (m > 0.f) ? (127.0f / m) : 0.f;
    #pragma unroll
    for (int j = 0; j < 4; j++) {
        int q0 = __float2int_rn(v[j].x * inv);
        int q1 = __float2int_rn(v[j].y * inv);
        int q2 = __float2int_rn(v[j].z * inv);
        int q3 = __float2int_rn(v[j].w * inv);
        uint32_t p = (uint32_t)(q0 & 0xff) | ((uint32_t)(q1 & 0xff) << 8) |
                     ((uint32_t)(q2 & 0xff) << 16) | ((uint32_t)(q3 & 0xff) << 24);
        qdst[j * 32 + lane] = p;
    }
    if (lane == 0) *sdst = m * (1.0f / 127.0f);
}

// ---------------------------------------------------------------------------
// Kernel 2: C[8192,512] = (Aq sa) @ (Bq sb)^T + residual (gathered epilogue)
// int8 mma.sync m16n8k32: half the mma count, half the bytes vs bf16.
// BM=128, BN=256, BK=128 int8 (4 ktiles), 3-stage cp.async, 256 threads,
// 8 warps (2x4), warp tile 64x64. Grid (2,64) = 128 CTAs = one wave.
// ---------------------------------------------------------------------------
#define BM 128
#define BN 256
#define BKB 128                      // K-bytes per ktile (int8)
#define KPB 144                      // smem row stride (bytes): conflict-free
#define STAGES 3
#define ASZB (BM * KPB)              // 18432 B
#define BSZB (BN * KPB)              // 36864 B
#define STAGEB (ASZB + BSZB)
#define SMEM_BYTES (STAGES * STAGEB) // 165,888 B

__device__ __forceinline__ void cpa16(void* sm, const void* g) {
    uint32_t s = (uint32_t)__cvta_generic_to_shared(sm);
    asm volatile("cp.async.cg.shared.global [%0], [%1], 16;\n" :: "r"(s), "l"(g));
}
__device__ __forceinline__ void ldsm_x4(uint32_t& d0, uint32_t& d1,
                                        uint32_t& d2, uint32_t& d3, uint32_t a) {
    asm volatile("ldmatrix.sync.aligned.m8n8.x4.shared.b16 {%0,%1,%2,%3}, [%4];"
                 : "=r"(d0), "=r"(d1), "=r"(d2), "=r"(d3) : "r"(a));
}

__global__ __launch_bounds__(256, 1)
void gemm_second_half(const int* __restrict__ ids,
                      const float* __restrict__ residual,   // [VOCAB][1024]
                      float* __restrict__ out) {            // [NTOK][1024]
    extern __shared__ char smem[];
    __shared__ int sids[BM];

    const int bn = blockIdx.x;        // 0..1
    const int bm = blockIdx.y;        // 0..63
    const int tid  = threadIdx.x;
    const int warp = tid >> 5;
    const int lane = tid & 31;
    const int wm = warp >> 2;         // 0..1  (64-row slab)
    const int wn = warp & 3;          // 0..3  (64-col slab)
    const int g  = lane >> 2;         // 0..7
    const int tg = lane & 3;          // 0..3

    if (tid < BM) sids[tid] = ids[bm * BM + tid];

    const uint32_t smem_b = (uint32_t)__cvta_generic_to_shared(smem);
    // ldmatrix per-lane byte offsets (b16-view of int8 k32 tiles)
    const uint32_t a_off = (uint32_t)((lane & 15) * KPB + ((lane >> 4) << 4));
    const uint32_t b_off = (uint32_t)(((lane & 7) + ((lane >> 4) << 3)) * KPB +
                                      (((lane >> 3) & 1) << 4));

    // ---- stage loader: A 128x128B + B 256x128B, 16B cp.async chunks ----
    auto load_stage = [&](int s, int ktb) {       // ktb = K byte offset
        char* As = smem + s * STAGEB;
        char* Bs = As + ASZB;
        #pragma unroll
        for (int i = 0; i < 4; i++) {             // A: 1024 chunks
            int c   = tid + i * 256;
            int row = c >> 3;
            int kc  = (c & 7) * 16;
            cpa16(As + row * KPB + kc,
                  g_Aq + (size_t)(bm * BM + row) * SMALLN + ktb + kc);
        }
        #pragma unroll
        for (int i = 0; i < 8; i++) {             // B: 2048 chunks
            int c   = tid + i * 256;
            int row = c >> 3;
            int kc  = (c & 7) * 16;
            cpa16(Bs + row * KPB + kc,
                  g_Bq + (size_t)(bn * BN + row) * SMALLN + ktb + kc);
        }
    };

    int acc[4][8][4];
    #pragma unroll
    for (int mi = 0; mi < 4; mi++)
        #pragma unroll
        for (int ni = 0; ni < 8; ni++)
            #pragma unroll
            for (int r = 0; r < 4; r++) acc[mi][ni][r] = 0;

    // ---- prologue: fill 2 stages ----
    load_stage(0, 0);
    asm volatile("cp.async.commit_group;\n");
    load_stage(1, BKB);
    asm volatile("cp.async.commit_group;\n");

    // ---- mainloop: 4 K-tiles (K=512 / 128) ----
    #pragma unroll 1
    for (int kt = 0; kt < 4; kt++) {
        asm volatile("cp.async.wait_group 1;\n");
        __syncthreads();

        if (kt + 2 < 4) load_stage((kt + 2) % STAGES, (kt + 2) * BKB);
        asm volatile("cp.async.commit_group;\n");

        const uint32_t As = smem_b + (uint32_t)((kt % STAGES) * STAGEB);
        const uint32_t Bs = As + ASZB;

        #pragma unroll
        for (int kh = 0; kh < 4; kh++) {          // k32 per step
            const int kkb = kh * 32;              // byte offset in row
            uint32_t af[4][4], bf[8][2];
            #pragma unroll
            for (int mi = 0; mi < 4; mi++) {
                int r0i = wm * 64 + mi * 16;
                ldsm_x4(af[mi][0], af[mi][1], af[mi][2], af[mi][3],
                        As + a_off + (uint32_t)(r0i * KPB + kkb));
            }
            #pragma unroll
            for (int nb = 0; nb < 4; nb++) {
                int n0 = wn * 64 + nb * 16;
                ldsm_x4(bf[nb * 2][0], bf[nb * 2][1],
                        bf[nb * 2 + 1][0], bf[nb * 2 + 1][1],
                        Bs + b_off + (uint32_t)(n0 * KPB + kkb));
            }
            #pragma unroll
            for (int mi = 0; mi < 4; mi++)
                #pragma unroll
                for (int ni = 0; ni < 8; ni++) {
                    asm volatile(
                        "mma.sync.aligned.m16n8k32.row.col.s32.s8.s8.s32 "
                        "{%0,%1,%2,%3}, {%4,%5,%6,%7}, {%8,%9}, {%0,%1,%2,%3};\n"
                        : "+r"(acc[mi][ni][0]), "+r"(acc[mi][ni][1]),
                          "+r"(acc[mi][ni][2]), "+r"(acc[mi][ni][3])
                        : "r"(af[mi][0]), "r"(af[mi][1]), "r"(af[mi][2]), "r"(af[mi][3]),
                          "r"(bf[ni][0]), "r"(bf[ni][1]));
                }
        }
    }

    // ---- epilogue: dequant + residual[id, 512+col] -> out[t, 512+col] ----
    #pragma unroll
    for (int mi = 0; mi < 4; mi++) {
        const int lr0 = wm * 64 + mi * 16 + g;
        const int t0  = bm * BM + lr0;
        const int id0 = sids[lr0];
        const int id1 = sids[lr0 + 8];
        const float sa0 = g_sa[bm * BM + lr0];
        const float sa1 = g_sa[bm * BM + lr0 + 8];
        #pragma unroll
        for (int ni = 0; ni < 8; ni++) {
            const int col = bn * BN + wn * 64 + ni * 8 + tg * 2;   // 0..511
            const float2 sbv = *reinterpret_cast<const float2*>(g_sb + col);
            {
                float2 rv = *reinterpret_cast<const float2*>(
                    residual + (size_t)id0 * LARGEN + SMALLN + col);
                float2 o;
                o.x = (float)acc[mi][ni][0] * (sa0 * sbv.x) + rv.x;
                o.y = (float)acc[mi][ni][1] * (sa0 * sbv.y) + rv.y;
                *reinterpret_cast<float2*>(
                    out + (size_t)t0 * LARGEN + SMALLN + col) = o;
            }
            {
                float2 rv = *reinterpret_cast<const float2*>(
                    residual + (size_t)id1 * LARGEN + SMALLN + col);
                float2 o;
                o.x = (float)acc[mi][ni][2] * (sa1 * sbv.x) + rv.x;
                o.y = (float)acc[mi][ni][3] * (sa1 * sbv.y) + rv.y;
                *reinterpret_cast<float2*>(
                    out + (size_t)(t0 + 8) * LARGEN + SMALLN + col) = o;
            }
        }
    }
}

// ---------------------------------------------------------------------------
// Launch
// ---------------------------------------------------------------------------
extern "C" void kernel_launch(void* const* d_in, const int* in_sizes, int n_in,
                              void* d_out, int out_size) {
    const int*   ids      = (const int*)  d_in[0];  // [4,2048]
    const float* weight   = (const float*)d_in[1];  // [50257,512]
    const float* cw       = (const float*)d_in[2];  // [512,512]
    const float* residual = (const float*)d_in[3];  // [50257,1024]
    float* out = (float*)d_out;                     // [8192,1024]

    cudaFuncSetAttribute(gemm_second_half,
                         cudaFuncAttributeMaxDynamicSharedMemorySize, SMEM_BYTES);

    // warp-per-row prep: first-half out + int8 quantization of A and cw
    prep_kernel<<<PREP_BLOCKS, 256>>>(
        ids,
        reinterpret_cast<const float4*>(weight),
        reinterpret_cast<const float4*>(residual),
        reinterpret_cast<const float4*>(cw),
        reinterpret_cast<float4*>(out));

    // int8 pipelined GEMM + dequant + residual epilogue (one wave: 128 CTAs)
    {
        dim3 grid(SMALLN / BN, NTOK / BM);          // (2, 64)
        gemm_second_half<<<grid, 256, SMEM_BYTES>>>(ids, residual, out);
    }
}

// round 12
// speedup vs baseline: 1.2355x; 1.2355x over previous
#include <cuda_runtime.h>
#include <cuda_bf16.h>
#include <cstdint>

// Problem constants
#define VOCABN 50257
#define SMALLN 512
#define LARGEN 1024
#define NTOK   8192      // B*S = 4*2048

// bf16 staging buffers (device globals: allocation-free scratch)
__device__ __nv_bfloat16 g_Abf[NTOK * SMALLN];    // gathered weight rows, bf16
__device__ __nv_bfloat16 g_Bbf[SMALLN * SMALLN];  // cw, bf16

// ---------------------------------------------------------------------------
// Kernel 1 (staging only): Abf = bf16(weight[ids]), Bbf = bf16(cw).
// Unit = 8 elements (one 16B bf16 store). ~27 MB traffic, ~3.5 us.
// ---------------------------------------------------------------------------
#define A_UNITS (NTOK * 64)              // 524288
#define B_UNITS (SMALLN * 64)            // 32768
#define PREP_UNITS (A_UNITS + B_UNITS)   // 557056

__global__ void prepA_kernel(const int* __restrict__ ids,
                             const float4* __restrict__ w4,     // [VOCAB][128]
                             const float4* __restrict__ cw4) {  // [512][128]
    int u = blockIdx.x * blockDim.x + threadIdx.x;
    float4 v0, v1;
    uint4* dst;
    if (u < A_UNITS) {
        int t = u >> 6;
        int c8 = u & 63;
        int id = ids[t];
        v0 = w4[(size_t)id * 128 + c8 * 2];
        v1 = w4[(size_t)id * 128 + c8 * 2 + 1];
        dst = reinterpret_cast<uint4*>(g_Abf + (size_t)t * SMALLN + c8 * 8);
    } else {
        int i = u - A_UNITS;
        v0 = cw4[(size_t)i * 2];
        v1 = cw4[(size_t)i * 2 + 1];
        dst = reinterpret_cast<uint4*>(g_Bbf + (size_t)i * 8);
    }
    __nv_bfloat162 p0 = {__float2bfloat16(v0.x), __float2bfloat16(v0.y)};
    __nv_bfloat162 p1 = {__float2bfloat16(v0.z), __float2bfloat16(v0.w)};
    __nv_bfloat162 p2 = {__float2bfloat16(v1.x), __float2bfloat16(v1.y)};
    __nv_bfloat162 p3 = {__float2bfloat16(v1.z), __float2bfloat16(v1.w)};
    uint4 pack;
    pack.x = *reinterpret_cast<uint32_t*>(&p0);
    pack.y = *reinterpret_cast<uint32_t*>(&p1);
    pack.z = *reinterpret_cast<uint32_t*>(&p2);
    pack.w = *reinterpret_cast<uint32_t*>(&p3);
    *dst = pack;
}

// ---------------------------------------------------------------------------
// Kernel 2: heterogeneous grid.
//  bids [0,128):   R9 GEMM: C[8192,512] = Abf @ Bbf^T + residual epilogue
//                  (BM=128, BN=256, BK=64, 64x64 warp tiles, 3-stage cp.async)
//  bids [128,192): copy CTAs: out[t,0:512] = weight[id] + residual[id,0:512]
//                  running on the ~20 spare SMs, hidden under the GEMM.
// ---------------------------------------------------------------------------
#define GEMM_CTAS 128
#define COPY_CTAS 64
#define TOTAL_CTAS (GEMM_CTAS + COPY_CTAS)

#define BM 128
#define BN 256
#define BK 64
#define KP 72                       // padded smem row stride (bf16); 144B
#define STAGES 3
#define ASZ (BM * KP)
#define BSZ (BN * KP)
#define STAGE_ELEMS (ASZ + BSZ)
#define SMEM_BYTES (STAGES * STAGE_ELEMS * 2)   // 165,888 B

// copy partition: NTOK*128 float4-units over 64 CTAs of 256 threads
#define COPY_UNITS (NTOK * 128)                 // 1,048,576
#define COPY_PER_CTA (COPY_UNITS / COPY_CTAS)   // 16384
#define COPY_ITERS (COPY_PER_CTA / 256)         // 64

__device__ __forceinline__ void cpa16(void* sm, const void* g) {
    uint32_t s = (uint32_t)__cvta_generic_to_shared(sm);
    asm volatile("cp.async.cg.shared.global [%0], [%1], 16;\n" :: "r"(s), "l"(g));
}
__device__ __forceinline__ void ldsm_x4(uint32_t& d0, uint32_t& d1,
                                        uint32_t& d2, uint32_t& d3, uint32_t a) {
    asm volatile("ldmatrix.sync.aligned.m8n8.x4.shared.b16 {%0,%1,%2,%3}, [%4];"
                 : "=r"(d0), "=r"(d1), "=r"(d2), "=r"(d3) : "r"(a));
}

__global__ __launch_bounds__(256, 1)
void gemm_plus_copy(const int* __restrict__ ids,
                    const float* __restrict__ weight,     // [VOCAB][512]
                    const float* __restrict__ residual,   // [VOCAB][1024]
                    float* __restrict__ out) {            // [NTOK][1024]
    const int bid = blockIdx.x;
    const int tid = threadIdx.x;

    // ======================= COPY CTAs =======================
    if (bid >= GEMM_CTAS) {
        const int cc = bid - GEMM_CTAS;            // 0..63
        const float4* w4 = reinterpret_cast<const float4*>(weight);
        const float4* r4 = reinterpret_cast<const float4*>(residual);
        float4* out4 = reinterpret_cast<float4*>(out);
        #pragma unroll 4
        for (int i = 0; i < COPY_ITERS; i++) {
            int u = cc * COPY_PER_CTA + i * 256 + tid;
            int t = u >> 7;                        // token
            int c = u & 127;                       // float4 col (0..127)
            int id = ids[t];
            float4 a = w4[(size_t)id * 128 + c];
            float4 b = r4[(size_t)id * 256 + c];
            float4 o;
            o.x = a.x + b.x; o.y = a.y + b.y;
            o.z = a.z + b.z; o.w = a.w + b.w;
            // out row stride 1024 floats = 256 float4
            out4[(size_t)t * 256 + c] = o;
        }
        return;
    }

    // ======================= GEMM CTAs =======================
    extern __shared__ __nv_bfloat16 smem[];
    __shared__ int sids[BM];

    const int bn = bid & 1;           // 0..1
    const int bm = bid >> 1;          // 0..63
    const int warp = tid >> 5;
    const int lane = tid & 31;
    const int wm = warp >> 2;         // 0..1  (64-row slab)
    const int wn = warp & 3;          // 0..3  (64-col slab)
    const int g  = lane >> 2;         // 0..7
    const int tg = lane & 3;          // 0..3

    if (tid < BM) sids[tid] = ids[bm * BM + tid];

    const uint32_t smem_b = (uint32_t)__cvta_generic_to_shared(smem);
    const uint32_t a_off = (uint32_t)(((lane & 15) * KP + ((lane >> 4) << 3)) * 2);
    const uint32_t b_off = (uint32_t)((((lane & 7) + ((lane >> 4) << 3)) * KP +
                                      (((lane >> 3) & 1) << 3)) * 2);

    auto load_stage = [&](int s, int kt) {
        __nv_bfloat16* As = smem + s * STAGE_ELEMS;
        __nv_bfloat16* Bs = As + ASZ;
        #pragma unroll
        for (int i = 0; i < 4; i++) {                // A: 1024 chunks
            int c   = tid + i * 256;
            int row = c >> 3;
            int kc  = (c & 7) * 8;
            cpa16(As + row * KP + kc,
                  g_Abf + (size_t)(bm * BM + row) * SMALLN + kt + kc);
        }
        #pragma unroll
        for (int i = 0; i < 8; i++) {                // B: 2048 chunks
            int c   = tid + i * 256;
            int row = c >> 3;
            int kc  = (c & 7) * 8;
            cpa16(Bs + row * KP + kc,
                  g_Bbf + (size_t)(bn * BN + row) * SMALLN + kt + kc);
        }
    };

    float acc[4][8][4];
    #pragma unroll
    for (int mi = 0; mi < 4; mi++)
        #pragma unroll
        for (int ni = 0; ni < 8; ni++)
            #pragma unroll
            for (int r = 0; r < 4; r++) acc[mi][ni][r] = 0.f;

    // ---- prologue: fill 2 stages ----
    load_stage(0, 0);
    asm volatile("cp.async.commit_group;\n");
    load_stage(1, BK);
    asm volatile("cp.async.commit_group;\n");

    // ---- mainloop: 8 K-tiles ----
    #pragma unroll 1
    for (int kt8 = 0; kt8 < 8; kt8++) {
        asm volatile("cp.async.wait_group 1;\n");
        __syncthreads();

        if (kt8 + 2 < 8) load_stage((kt8 + 2) % STAGES, (kt8 + 2) * BK);
        asm volatile("cp.async.commit_group;\n");

        const uint32_t As = smem_b + (uint32_t)((kt8 % STAGES) * STAGE_ELEMS) * 2;
        const uint32_t Bs = As + ASZ * 2;

        #pragma unroll
        for (int kh = 0; kh < 4; kh++) {
            const int kk = kh * 16;
            uint32_t af[4][4], bf[8][2];
            #pragma unroll
            for (int mi = 0; mi < 4; mi++) {
                int r0i = wm * 64 + mi * 16;
                ldsm_x4(af[mi][0], af[mi][1], af[mi][2], af[mi][3],
                        As + a_off + (uint32_t)((r0i * KP + kk) * 2));
            }
            #pragma unroll
            for (int nb = 0; nb < 4; nb++) {
                int n0 = wn * 64 + nb * 16;
                ldsm_x4(bf[nb * 2][0], bf[nb * 2][1],
                        bf[nb * 2 + 1][0], bf[nb * 2 + 1][1],
                        Bs + b_off + (uint32_t)((n0 * KP + kk) * 2));
            }
            #pragma unroll
            for (int mi = 0; mi < 4; mi++)
                #pragma unroll
                for (int ni = 0; ni < 8; ni++) {
                    asm volatile(
                        "mma.sync.aligned.m16n8k16.row.col.f32.bf16.bf16.f32 "
                        "{%0,%1,%2,%3}, {%4,%5,%6,%7}, {%8,%9}, {%0,%1,%2,%3};\n"
                        : "+f"(acc[mi][ni][0]), "+f"(acc[mi][ni][1]),
                          "+f"(acc[mi][ni][2]), "+f"(acc[mi][ni][3])
                        : "r"(af[mi][0]), "r"(af[mi][1]), "r"(af[mi][2]), "r"(af[mi][3]),
                          "r"(bf[ni][0]), "r"(bf[ni][1]));
                }
        }
    }

    // ---- epilogue: + residual[id, 512+col] -> out[t, 512+col] ----
    #pragma unroll
    for (int mi = 0; mi < 4; mi++) {
        const int lr0 = wm * 64 + mi * 16 + g;
        const int t0  = bm * BM + lr0;
        const int id0 = sids[lr0];
        const int id1 = sids[lr0 + 8];
        #pragma unroll
        for (int ni = 0; ni < 8; ni++) {
            const int col = bn * BN + wn * 64 + ni * 8 + tg * 2;   // 0..511
            {
                float2 rv = *reinterpret_cast<const float2*>(
                    residual + (size_t)id0 * LARGEN + SMALLN + col);
                float2 o;
                o.x = acc[mi][ni][0] + rv.x;
                o.y = acc[mi][ni][1] + rv.y;
                *reinterpret_cast<float2*>(
                    out + (size_t)t0 * LARGEN + SMALLN + col) = o;
            }
            {
                float2 rv = *reinterpret_cast<const float2*>(
                    residual + (size_t)id1 * LARGEN + SMALLN + col);
                float2 o;
                o.x = acc[mi][ni][2] + rv.x;
                o.y = acc[mi][ni][3] + rv.y;
                *reinterpret_cast<float2*>(
                    out + (size_t)(t0 + 8) * LARGEN + SMALLN + col) = o;
            }
        }
    }
}

// ---------------------------------------------------------------------------
// Launch
// ---------------------------------------------------------------------------
extern "C" void kernel_launch(void* const* d_in, const int* in_sizes, int n_in,
                              void* d_out, int out_size) {
    const int*   ids      = (const int*)  d_in[0];  // [4,2048]
    const float* weight   = (const float*)d_in[1];  // [50257,512]
    const float* cw       = (const float*)d_in[2];  // [512,512]
    const float* residual = (const float*)d_in[3];  // [50257,1024]
    float* out = (float*)d_out;                     // [8192,1024]

    cudaFuncSetAttribute(gemm_plus_copy,
                         cudaFuncAttributeMaxDynamicSharedMemorySize, SMEM_BYTES);

    // staging-only prep: Abf + Bbf
    prepA_kernel<<<PREP_UNITS / 256, 256>>>(
        ids,
        reinterpret_cast<const float4*>(weight),
        reinterpret_cast<const float4*>(cw));

    // heterogeneous launch: 128 GEMM CTAs (wave-1) + 64 copy CTAs (spare SMs)
    gemm_plus_copy<<<TOTAL_CTAS, 256, SMEM_BYTES>>>(ids, weight, residual, out);
}